// round 1
// baseline (speedup 1.0000x reference)
#include <cuda_runtime.h>
#include <cuda_bf16.h>

#define NN 50000
#define EE 800000
#define FF 128
#define HH 256
#define CC 40
#define NB ((NN + 1023) / 1024)   // 49 scan blocks

// ---------------- scratch (device globals; no runtime allocation) ----------
__device__ float g_bufA[(size_t)NN * HH];   // h1 / h2
__device__ float g_bufB[(size_t)NN * HH];   // relu(agg1) / agg2
__device__ int   g_deg[NN];
__device__ float g_dinv[NN];
__device__ int   g_rowptr[NN];
__device__ int   g_cursor[NN];
__device__ int   g_partials[64];
__device__ int   g_csrc[EE];

// ---------------- CSR build ------------------------------------------------
__global__ void zero_deg_kernel() {
    int i = blockIdx.x * blockDim.x + threadIdx.x;
    if (i < NN) g_deg[i] = 0;
}

__global__ void count_deg_kernel(const int* __restrict__ dst) {
    int e = blockIdx.x * blockDim.x + threadIdx.x;
    if (e < EE) atomicAdd(&g_deg[dst[e]], 1);
}

__global__ void dinv_kernel() {
    int i = blockIdx.x * blockDim.x + threadIdx.x;
    if (i < NN) g_dinv[i] = rsqrtf((float)g_deg[i] + 1.0f);
}

__global__ void scan_blocks_kernel() {
    __shared__ int sh[1024];
    int t = threadIdx.x;
    int i = blockIdx.x * 1024 + t;
    int v = (i < NN) ? g_deg[i] : 0;
    sh[t] = v;
    __syncthreads();
    #pragma unroll
    for (int off = 1; off < 1024; off <<= 1) {
        int add = (t >= off) ? sh[t - off] : 0;
        __syncthreads();
        sh[t] += add;
        __syncthreads();
    }
    if (i < NN) g_rowptr[i] = sh[t] - v;   // exclusive prefix
    if (t == 1023) g_partials[blockIdx.x] = sh[1023];
}

__global__ void scan_partials_kernel() {
    if (threadIdx.x == 0 && blockIdx.x == 0) {
        int acc = 0;
        for (int b = 0; b < NB; b++) {
            int t = g_partials[b];
            g_partials[b] = acc;
            acc += t;
        }
    }
}

__global__ void add_offsets_kernel() {
    int i = blockIdx.x * blockDim.x + threadIdx.x;
    if (i < NN) {
        int v = g_rowptr[i] + g_partials[i >> 10];
        g_rowptr[i] = v;
        g_cursor[i] = v;
    }
}

__global__ void fill_csr_kernel(const int* __restrict__ src, const int* __restrict__ dst) {
    int e = blockIdx.x * blockDim.x + threadIdx.x;
    if (e < EE) {
        int pos = atomicAdd(&g_cursor[dst[e]], 1);
        g_csrc[pos] = src[e];
    }
}

// ---------------- GEMM: C[M,N] = A[M,K] * B[N,K]^T (+bias) -----------------
#define BM 128
#define BN 128
#define BK 16
#define PAD 4

__global__ __launch_bounds__(256)
void gemm_nt_kernel(const float* __restrict__ A, const float* __restrict__ B,
                    const float* __restrict__ bias, float* __restrict__ C,
                    int M, int N, int K) {
    __shared__ float As[BK][BM + PAD];
    __shared__ float Bs[BK][BN + PAD];

    int bm = blockIdx.y * BM;
    int bn = blockIdx.x * BN;
    int tid = threadIdx.x;          // 0..255
    int tx = tid & 15;              // 0..15
    int ty = tid >> 4;              // 0..15

    float acc[8][8];
    #pragma unroll
    for (int i = 0; i < 8; i++)
        #pragma unroll
        for (int j = 0; j < 8; j++) acc[i][j] = 0.0f;

    for (int k0 = 0; k0 < K; k0 += BK) {
        // load A tile: 128 rows x 16 k = 512 float4s over 256 threads
        #pragma unroll
        for (int idx = tid; idx < BM * BK / 4; idx += 256) {
            int r = idx >> 2;
            int kq = idx & 3;
            int m = bm + r;
            float4 v = make_float4(0.f, 0.f, 0.f, 0.f);
            if (m < M) v = *(const float4*)&A[(size_t)m * K + k0 + kq * 4];
            As[kq * 4 + 0][r] = v.x;
            As[kq * 4 + 1][r] = v.y;
            As[kq * 4 + 2][r] = v.z;
            As[kq * 4 + 3][r] = v.w;
        }
        #pragma unroll
        for (int idx = tid; idx < BN * BK / 4; idx += 256) {
            int r = idx >> 2;
            int kq = idx & 3;
            int n = bn + r;
            float4 v = make_float4(0.f, 0.f, 0.f, 0.f);
            if (n < N) v = *(const float4*)&B[(size_t)n * K + k0 + kq * 4];
            Bs[kq * 4 + 0][r] = v.x;
            Bs[kq * 4 + 1][r] = v.y;
            Bs[kq * 4 + 2][r] = v.z;
            Bs[kq * 4 + 3][r] = v.w;
        }
        __syncthreads();

        #pragma unroll
        for (int kk = 0; kk < BK; kk++) {
            float a[8], b[8];
            *(float4*)&a[0] = *(const float4*)&As[kk][ty * 8];
            *(float4*)&a[4] = *(const float4*)&As[kk][ty * 8 + 4];
            *(float4*)&b[0] = *(const float4*)&Bs[kk][tx * 8];
            *(float4*)&b[4] = *(const float4*)&Bs[kk][tx * 8 + 4];
            #pragma unroll
            for (int i = 0; i < 8; i++)
                #pragma unroll
                for (int j = 0; j < 8; j++)
                    acc[i][j] += a[i] * b[j];
        }
        __syncthreads();
    }

    #pragma unroll
    for (int i = 0; i < 8; i++) {
        int m = bm + ty * 8 + i;
        if (m >= M) continue;
        #pragma unroll
        for (int j = 0; j < 8; j++) {
            int n = bn + tx * 8 + j;
            if (n < N) {
                float v = acc[i][j];
                if (bias) v += bias[n];
                C[(size_t)m * N + n] = v;
            }
        }
    }
}

// ---------------- aggregation: block per node, 256 channels ----------------
__global__ __launch_bounds__(256)
void aggregate_kernel(const float* __restrict__ h, const float* __restrict__ bias,
                      float* __restrict__ out, int relu) {
    int i = blockIdx.x;
    int c = threadIdx.x;
    __shared__ int   s_src[256];
    __shared__ float s_w[256];

    int start = g_rowptr[i];
    int d = g_deg[i];
    float di = g_dinv[i];
    float acc = 0.0f;

    for (int base = 0; base < d; base += 256) {
        int n = d - base;
        if (n > 256) n = 256;
        __syncthreads();
        if (c < n) {
            int s = g_csrc[start + base + c];
            s_src[c] = s;
            s_w[c] = g_dinv[s];
        }
        __syncthreads();
        #pragma unroll 4
        for (int j = 0; j < n; j++)
            acc += s_w[j] * h[(size_t)s_src[j] * HH + c];
    }

    float v = di * acc + di * di * h[(size_t)i * HH + c] + bias[c];
    if (relu) v = fmaxf(v, 0.0f);
    out[(size_t)i * HH + c] = v;
}

// ---------------- launch ---------------------------------------------------
extern "C" void kernel_launch(void* const* d_in, const int* in_sizes, int n_in,
                              void* d_out, int out_size) {
    const float* x    = (const float*)d_in[0];
    const int*   ei   = (const int*)d_in[1];
    const float* W1   = (const float*)d_in[2];
    const float* b1   = (const float*)d_in[3];
    const float* W2   = (const float*)d_in[4];
    const float* b2   = (const float*)d_in[5];
    const float* Wout = (const float*)d_in[6];
    const float* bout = (const float*)d_in[7];
    float* out = (float*)d_out;

    const int* src = ei;         // edge_index[0]
    const int* dst = ei + EE;    // edge_index[1]

    float* bufA;  cudaGetSymbolAddress((void**)&bufA, g_bufA);
    float* bufB;  cudaGetSymbolAddress((void**)&bufB, g_bufB);

    // ---- CSR build ----
    zero_deg_kernel<<<(NN + 255) / 256, 256>>>();
    count_deg_kernel<<<(EE + 255) / 256, 256>>>(dst);
    dinv_kernel<<<(NN + 255) / 256, 256>>>();
    scan_blocks_kernel<<<NB, 1024>>>();
    scan_partials_kernel<<<1, 32>>>();
    add_offsets_kernel<<<(NN + 255) / 256, 256>>>();
    fill_csr_kernel<<<(EE + 255) / 256, 256>>>(src, dst);

    // ---- layer 1: h1 = x @ W1^T ; bufB = relu(agg(h1) + b1) ----
    {
        dim3 grid((HH + BN - 1) / BN, (NN + BM - 1) / BM);
        gemm_nt_kernel<<<grid, 256>>>(x, W1, nullptr, bufA, NN, HH, FF);
        aggregate_kernel<<<NN, 256>>>(bufA, b1, bufB, 1);
    }

    // ---- layer 2: h2 = bufB @ W2^T ; bufA reused for h2 output -> agg into bufB? ----
    // h2 -> bufA ; agg2 -> reuse of bufB is unsafe (bufB is the gemm input has been fully
    // consumed only after gemm completes; aggregate reads bufA and writes a distinct buffer).
    // We write agg2 back into bufB after gemm2 finished reading it (sequential stream order).
    {
        dim3 grid((HH + BN - 1) / BN, (NN + BM - 1) / BM);
        gemm_nt_kernel<<<grid, 256>>>(bufB, W2, nullptr, bufA, NN, HH, HH);
        aggregate_kernel<<<NN, 256>>>(bufA, b2, bufB, 0);
    }

    // ---- output: out = bufB @ Wout^T + bout ----
    {
        dim3 grid((CC + BN - 1) / BN, (NN + BM - 1) / BM);
        gemm_nt_kernel<<<grid, 256>>>(bufB, Wout, bout, out, NN, CC, HH);
    }
}